// round 16
// baseline (speedup 1.0000x reference)
#include <cuda_runtime.h>
#include <cuda_bf16.h>
#include <cstdint>

#define HID 128
#define NH 4
#define NB 60000
#define NP 2000
#define NC 4000
#define EM_N 150000
#define EP_N 300000
#define EI_N 150000
#define NTILE 469          // ceil(NB/128)
#define PTILE 16           // ceil(NP/128)
#define CTILE 32           // ceil(NC/128)

// edge pass block counts (4 edges/warp, 8 warps/block => 32 edges/block)
#define BG1 ((EM_N/4 + 7)/8)
#define BT1 ((EP_N/4 + 7)/8)
#define BS1 ((EI_N/4 + 7)/8)

// setup kernel partition
#define ZB ((NB*NH + 255)/256)
#define PB ((8*16384 + 255)/256)
#define SETUP_GRID (ZB + PB)

// zero kernel: GATACC + TRACC + CTXSUM + CNT (contiguous)
#define ZTOT (2*NB*HID + NC*HID + NC)
#define ZERO_GRID ((ZTOT/4 + 255)/256)

// ---- scratch layout (floats); CNT directly follows CTXSUM ----
#define SZ_NBH (NB*HID)
#define OFF_XL     0
#define OFF_XR     (OFF_XL + NP*HID)
#define OFF_Q      (OFF_XR + SZ_NBH)
#define OFF_K      (OFF_Q + SZ_NBH)
#define OFF_V      (OFF_K + SZ_NBH)
#define OFF_SKIP   (OFF_V + SZ_NBH)
#define OFF_GATACC (OFF_SKIP + SZ_NBH)
#define OFF_TRACC  (OFF_GATACC + SZ_NBH)
#define OFF_CTXSUM (OFF_TRACC + SZ_NBH)
#define OFF_CNT    (OFF_CTXSUM + NC*HID)
#define OFF_SAGE   (OFF_CNT + NC)
#define OFF_GSUM   (OFF_SAGE + NC*HID)
#define OFF_TSUM   (OFF_GSUM + NB*NH)
#define TOTAL_SCRATCH (OFF_TSUM + NB*NH)

__device__ __align__(256) float g_buf[TOTAL_SCRATCH];

// pre-converted weights: 8 matrices x {hi,lo}; order: 0=q,1=k,2=v,3=skip,4=gWr,5=gWl,6=sWr,7=sWl
#define STR 136
#define WP_ELEMS (128*STR)
__device__ __align__(1024) __nv_bfloat16 g_Wprep[8*2*WP_ELEMS];

// ---------------- PTX helpers ----------------
__device__ __forceinline__ uint32_t smem_u32(const void* p) {
    uint32_t a;
    asm("{ .reg .u64 t; cvta.to.shared.u64 t, %1; cvt.u32.u64 %0, t; }" : "=r"(a) : "l"(p));
    return a;
}
__device__ __forceinline__ void ldsm4(uint32_t& r0, uint32_t& r1, uint32_t& r2, uint32_t& r3,
                                      uint32_t addr) {
    asm volatile("ldmatrix.sync.aligned.m8n8.x4.shared.b16 {%0,%1,%2,%3}, [%4];"
                 : "=r"(r0), "=r"(r1), "=r"(r2), "=r"(r3) : "r"(addr));
}
__device__ __forceinline__ void ldsm4t(uint32_t& r0, uint32_t& r1, uint32_t& r2, uint32_t& r3,
                                       uint32_t addr) {
    asm volatile("ldmatrix.sync.aligned.m8n8.x4.trans.shared.b16 {%0,%1,%2,%3}, [%4];"
                 : "=r"(r0), "=r"(r1), "=r"(r2), "=r"(r3) : "r"(addr));
}
__device__ __forceinline__ void mma16816(float* C, const uint32_t* A, uint32_t B0, uint32_t B1) {
    asm volatile("mma.sync.aligned.m16n8k16.row.col.f32.bf16.bf16.f32 "
                 "{%0,%1,%2,%3}, {%4,%5,%6,%7}, {%8,%9}, {%0,%1,%2,%3};"
                 : "+f"(C[0]), "+f"(C[1]), "+f"(C[2]), "+f"(C[3])
                 : "r"(A[0]), "r"(A[1]), "r"(A[2]), "r"(A[3]), "r"(B0), "r"(B1));
}
#define CP_ASYNC16(sm, gm) \
    asm volatile("cp.async.ca.shared.global [%0], [%1], 16;" :: "r"(sm), "l"(gm))
#define CP_COMMIT() asm volatile("cp.async.commit_group;" ::: "memory")
#define CP_WAIT1() asm volatile("cp.async.wait_group 1;" ::: "memory")
#define CP_WAIT0() asm volatile("cp.async.wait_group 0;" ::: "memory")

// ---------------- setup: zero gsum/tsum + weight prep ----------------
__global__ void setup_kernel(const float* __restrict__ w0, const float* __restrict__ w1,
                             const float* __restrict__ w2, const float* __restrict__ w3,
                             const float* __restrict__ w4, const float* __restrict__ w5,
                             const float* __restrict__ w6, const float* __restrict__ w7)
{
    unsigned b = blockIdx.x;
    if (b < ZB) {
        int i = b * 256 + threadIdx.x;
        if (i < NB*NH) {
            g_buf[OFF_GSUM + i] = 0.f;
            g_buf[OFF_TSUM + i] = 0.f;
        }
    } else {
        int idx = (b - ZB) * 256 + threadIdx.x;
        if (idx >= 8 * 16384) return;
        int m = idx >> 14, rem = idx & 16383;
        int k = rem >> 7, n = rem & 127;
        const float* W = (m == 0) ? w0 : (m == 1) ? w1 : (m == 2) ? w2 : (m == 3) ? w3
                       : (m == 4) ? w4 : (m == 5) ? w5 : (m == 6) ? w6 : w7;
        float v = W[(size_t)k * HID + n];
        __nv_bfloat16 hi = __float2bfloat16(v);
        __nv_bfloat16 lo = __float2bfloat16(v - __bfloat162float(hi));
        g_Wprep[(size_t)(m*2 + 0)*WP_ELEMS + k*STR + n] = hi;
        g_Wprep[(size_t)(m*2 + 1)*WP_ELEMS + k*STR + n] = lo;
    }
}

// ---------------- zero kernel (side stream) ----------------
__global__ void zero_kernel() {
    size_t i = ((size_t)blockIdx.x * 256 + threadIdx.x) * 4;
    if (i + 3 < ZTOT) {
        *(float4*)(g_buf + OFF_GATACC + i) = make_float4(0.f, 0.f, 0.f, 0.f);
    } else {
        for (size_t k = i; k < ZTOT; k++) g_buf[OFF_GATACC + k] = 0.f;
    }
}

// ---------------- split HMMA GEMM ----------------
// mode 0: xr (ball tiles) + xl (player tiles);  mode 1: q,k,v,skip (ball tiles)
#define SMA_H 0
#define SMA_L 34816
#define SMW0  69632
#define SMW1  139264
#define SMEM_BIG 208896

__device__ __forceinline__ void stageW_async(uint32_t smW, int widx, int tid) {
    const char* gh = (const char*)g_Wprep + (size_t)(widx*2)*WP_ELEMS*2;
    const char* gl = gh + WP_ELEMS*2;
    for (int j = tid; j < 2176; j += 256) {
        CP_ASYNC16(smW + j*16, gh + j*16);
        CP_ASYNC16(smW + 34816 + j*16, gl + j*16);
    }
}

__global__ void __launch_bounds__(256)
big_mma(int mode,
        const float* __restrict__ xball, const float* __restrict__ xplayer,
        float* __restrict__ o_q, float* __restrict__ o_k, float* __restrict__ o_v,
        float* __restrict__ o_skip, float* __restrict__ o_xr, float* __restrict__ o_xl,
        const float* __restrict__ b0, const float* __restrict__ b1,
        const float* __restrict__ b2, const float* __restrict__ b3)
{
    extern __shared__ char smem[];
    const uint32_t sb = smem_u32(smem);
    const int tid = threadIdx.x, lane = tid & 31, warp = tid >> 5;
    const int wm = warp >> 1, wn = warp & 1;
    const bool player = (mode == 0) && (blockIdx.x >= NTILE);
    const int tile = player ? (blockIdx.x - NTILE) : blockIdx.x;
    const int rbase = tile * 128;
    const int nrows = player ? NP : NB;
    const float* Asrc = player ? xplayer : xball;
    const int wfirst = (mode == 0) ? (player ? 5 : 4) : 0;
    const int nw = (mode == 0) ? 1 : 4;

    // stage A tile as hi/lo bf16
    for (int idx = tid; idx < 8192; idx += 256) {
        int row = idx >> 6, kp = idx & 63;
        int grow = rbase + row;
        float2 v = make_float2(0.f, 0.f);
        if (grow < nrows) v = ((const float2*)(Asrc + (size_t)grow * HID))[kp];
        __nv_bfloat162 h2 = __float22bfloat162_rn(v);
        float2 lo = make_float2(v.x - __bfloat162float(h2.x),
                                v.y - __bfloat162float(h2.y));
        __nv_bfloat162 l2 = __float22bfloat162_rn(lo);
        uint32_t off = (uint32_t)(row * STR + kp * 2) * 2;
        *(uint32_t*)(smem + SMA_H + off) = *(uint32_t*)&h2;
        *(uint32_t*)(smem + SMA_L + off) = *(uint32_t*)&l2;
    }

    stageW_async(sb + SMW0, wfirst, tid);
    CP_COMMIT();

    float*       outs4[4]   = {o_q, o_k, o_v, o_skip};
    const float* biases4[4] = {b0, b1, b2, b3};

    const int gid = lane >> 2, tig = lane & 3;
    const int sub = lane >> 3, lr = lane & 7;
    const int f_r = ((sub & 1) << 3) + lr;
    const int f_c = (sub >> 1) << 3;

    for (int i = 0; i < nw; i++) {
        if (i + 1 < nw) {
            stageW_async(sb + (((i+1) & 1) ? SMW1 : SMW0), wfirst + i + 1, tid);
            CP_COMMIT();
            CP_WAIT1();
        } else {
            CP_WAIT0();
        }
        __syncthreads();

        const uint32_t wbase = sb + ((i & 1) ? SMW1 : SMW0);

        float acc[2][8][4];
        #pragma unroll
        for (int mt = 0; mt < 2; mt++)
            #pragma unroll
            for (int j = 0; j < 8; j++)
                #pragma unroll
                for (int c = 0; c < 4; c++) acc[mt][j][c] = 0.f;

        #pragma unroll
        for (int ks = 0; ks < 8; ks++) {
            const int K0 = ks * 16;
            uint32_t ah[2][4], al[2][4];
            #pragma unroll
            for (int mt = 0; mt < 2; mt++) {
                uint32_t ad = sb + SMA_H +
                    (uint32_t)((wm*32 + mt*16 + f_r) * STR + K0 + f_c) * 2;
                ldsm4(ah[mt][0], ah[mt][1], ah[mt][2], ah[mt][3], ad);
                ldsm4(al[mt][0], al[mt][1], al[mt][2], al[mt][3], ad + (SMA_L - SMA_H));
            }
            uint32_t bh[4][4], bl[4][4];
            #pragma unroll
            for (int nt = 0; nt < 4; nt++) {
                uint32_t wd = wbase +
                    (uint32_t)((K0 + f_r) * STR + wn*64 + nt*16 + f_c) * 2;
                ldsm4t(bh[nt][0], bh[nt][1], bh[nt][2], bh[nt][3], wd);
                ldsm4t(bl[nt][0], bl[nt][1], bl[nt][2], bl[nt][3], wd + 34816);
            }
            #pragma unroll
            for (int mt = 0; mt < 2; mt++)
                #pragma unroll
                for (int nt = 0; nt < 4; nt++)
                    #pragma unroll
                    for (int h = 0; h < 2; h++) {
                        float* C = acc[mt][nt*2 + h];
                        mma16816(C, ah[mt], bh[nt][2*h], bh[nt][2*h+1]);
                        mma16816(C, ah[mt], bl[nt][2*h], bl[nt][2*h+1]);
                        mma16816(C, al[mt], bh[nt][2*h], bh[nt][2*h+1]);
                    }
        }

        const float* bias = (mode == 1) ? biases4[i] : nullptr;
        float* outp = (mode == 0) ? (player ? o_xl : o_xr) : outs4[i];
        #pragma unroll
        for (int mt = 0; mt < 2; mt++) {
            int r0g = rbase + wm*32 + mt*16 + gid;
            #pragma unroll
            for (int j = 0; j < 8; j++) {
                int cn = wn*64 + j*8 + tig*2;
                float bx = bias ? bias[cn]   : 0.f;
                float by = bias ? bias[cn+1] : 0.f;
                if (r0g < nrows)
                    *(float2*)(outp + (size_t)r0g*HID + cn) =
                        make_float2(acc[mt][j][0] + bx, acc[mt][j][1] + by);
                if (r0g + 8 < nrows)
                    *(float2*)(outp + (size_t)(r0g+8)*HID + cn) =
                        make_float2(acc[mt][j][2] + bx, acc[mt][j][3] + by);
            }
        }
        __syncthreads();
    }
}

// ---------------- sage HMMA: s_sage = x_ctx@sWr + (ctxsum/cnt)@sWl + sbl ----------------
#define SMEM_SAGE 139264

__global__ void __launch_bounds__(256)
sage_mma(const float* __restrict__ xctx, float* __restrict__ outp,
         const float* __restrict__ sbl)
{
    extern __shared__ char smem[];
    const uint32_t sb = smem_u32(smem);
    const int tid = threadIdx.x, lane = tid & 31, warp = tid >> 5;
    const int wm = warp >> 1, wn = warp & 1;
    const int rbase = blockIdx.x * 128;

    const int gid = lane >> 2, tig = lane & 3;
    const int sub = lane >> 3, lr = lane & 7;
    const int f_r = ((sub & 1) << 3) + lr;
    const int f_c = (sub >> 1) << 3;

    float acc[2][8][4];
    #pragma unroll
    for (int mt = 0; mt < 2; mt++)
        #pragma unroll
        for (int j = 0; j < 8; j++)
            #pragma unroll
            for (int c = 0; c < 4; c++) acc[mt][j][c] = 0.f;

    for (int it = 0; it < 2; it++) {
        const int widx = 6 + it;
        for (int idx = tid; idx < 8192; idx += 256) {
            int row = idx >> 6, kp = idx & 63;
            int grow = rbase + row;
            float2 v = make_float2(0.f, 0.f);
            if (grow < NC) {
                if (it == 0) {
                    v = ((const float2*)(xctx + (size_t)grow * HID))[kp];
                } else {
                    v = ((const float2*)(g_buf + OFF_CTXSUM + (size_t)grow * HID))[kp];
                    float rc = 1.0f / fmaxf(g_buf[OFF_CNT + grow], 1.0f);
                    v.x *= rc; v.y *= rc;
                }
            }
            __nv_bfloat162 h2 = __float22bfloat162_rn(v);
            float2 lo = make_float2(v.x - __bfloat162float(h2.x),
                                    v.y - __bfloat162float(h2.y));
            __nv_bfloat162 l2 = __float22bfloat162_rn(lo);
            uint32_t off = (uint32_t)(row * STR + kp * 2) * 2;
            *(uint32_t*)(smem + SMA_H + off) = *(uint32_t*)&h2;
            *(uint32_t*)(smem + SMA_L + off) = *(uint32_t*)&l2;
        }
        {
            const uint4* gh = (const uint4*)((const char*)g_Wprep + (size_t)(widx*2)*WP_ELEMS*2);
            const uint4* gl = (const uint4*)((const char*)g_Wprep + (size_t)(widx*2+1)*WP_ELEMS*2);
            uint4* dh = (uint4*)(smem + SMW0);
            uint4* dl = (uint4*)(smem + SMW0 + 34816);
            for (int j = tid; j < 2176; j += 256) { dh[j] = gh[j]; dl[j] = gl[j]; }
        }
        __syncthreads();

        #pragma unroll
        for (int ks = 0; ks < 8; ks++) {
            const int K0 = ks * 16;
            uint32_t ah[2][4], al[2][4];
            #pragma unroll
            for (int mt = 0; mt < 2; mt++) {
                uint32_t ad = sb + SMA_H +
                    (uint32_t)((wm*32 + mt*16 + f_r) * STR + K0 + f_c) * 2;
                ldsm4(ah[mt][0], ah[mt][1], ah[mt][2], ah[mt][3], ad);
                ldsm4(al[mt][0], al[mt][1], al[mt][2], al[mt][3], ad + (SMA_L - SMA_H));
            }
            uint32_t bh[4][4], bl[4][4];
            #pragma unroll
            for (int nt = 0; nt < 4; nt++) {
                uint32_t wd = sb + SMW0 +
                    (uint32_t)((K0 + f_r) * STR + wn*64 + nt*16 + f_c) * 2;
                ldsm4t(bh[nt][0], bh[nt][1], bh[nt][2], bh[nt][3], wd);
                ldsm4t(bl[nt][0], bl[nt][1], bl[nt][2], bl[nt][3], wd + 34816);
            }
            #pragma unroll
            for (int mt = 0; mt < 2; mt++)
                #pragma unroll
                for (int nt = 0; nt < 4; nt++)
                    #pragma unroll
                    for (int h = 0; h < 2; h++) {
                        float* C = acc[mt][nt*2 + h];
                        mma16816(C, ah[mt], bh[nt][2*h], bh[nt][2*h+1]);
                        mma16816(C, ah[mt], bl[nt][2*h], bl[nt][2*h+1]);
                        mma16816(C, al[mt], bh[nt][2*h], bh[nt][2*h+1]);
                    }
        }
        __syncthreads();
    }

    #pragma unroll
    for (int mt = 0; mt < 2; mt++) {
        int r0g = rbase + wm*32 + mt*16 + gid;
        #pragma unroll
        for (int j = 0; j < 8; j++) {
            int cn = wn*64 + j*8 + tig*2;
            float bx = sbl[cn], by = sbl[cn+1];
            if (r0g < NC)
                *(float2*)(outp + (size_t)r0g*HID + cn) =
                    make_float2(acc[mt][j][0] + bx, acc[mt][j][1] + by);
            if (r0g + 8 < NC)
                *(float2*)(outp + (size_t)(r0g+8)*HID + cn) =
                    make_float2(acc[mt][j][2] + bx, acc[mt][j][3] + by);
        }
    }
}

// ---------------- helpers ----------------
__device__ __forceinline__ void redAdd4(float* p, float a, float b, float c, float d) {
    asm volatile("red.global.add.v4.f32 [%0], {%1,%2,%3,%4};"
                 :: "l"(p), "f"(a), "f"(b), "f"(c), "f"(d) : "memory");
}

// ================= GAT edge pass (side stream; overlaps bigB) =================
__global__ void __launch_bounds__(256)
edge_gat_kernel(const int* __restrict__ em, const float* __restrict__ att)
{
    const int lane = threadIdx.x & 31;
    const int warp = threadIdx.x >> 5;
    int e0 = (blockIdx.x * 8 + warp) << 2;
    if (e0 >= EM_N) return;
    int idx = 0;
    if (lane < 8) {
        int e = e0 + (lane & 3);
        if (e < EM_N) idx = em[(lane & 4) ? EM_N + e : e];
    }
    int ss[4], dd[4];
    #pragma unroll
    for (int j = 0; j < 4; j++) {
        ss[j] = __shfl_sync(0xffffffffu, idx, j);
        dd[j] = __shfl_sync(0xffffffffu, idx, 4 + j);
    }
    float4 at = ((const float4*)att)[lane];
    float4 xlv[4], xrv[4];
    #pragma unroll
    for (int j = 0; j < 4; j++) {
        if (e0 + j < EM_N) {
            xlv[j] = ((const float4*)(g_buf + OFF_XL + (size_t)ss[j]*HID))[lane];
            xrv[j] = ((const float4*)(g_buf + OFF_XR + (size_t)dd[j]*HID))[lane];
        }
    }
    #pragma unroll
    for (int j = 0; j < 4; j++) {
        if (e0 + j >= EM_N) break;
        float ex = xlv[j].x + xrv[j].x; ex = ex > 0.f ? ex : 0.2f*ex;
        float ey = xlv[j].y + xrv[j].y; ey = ey > 0.f ? ey : 0.2f*ey;
        float ez = xlv[j].z + xrv[j].z; ez = ez > 0.f ? ez : 0.2f*ez;
        float ew = xlv[j].w + xrv[j].w; ew = ew > 0.f ? ew : 0.2f*ew;
        float p = ex*at.x + ey*at.y + ez*at.z + ew*at.w;
        p += __shfl_xor_sync(0xffffffffu, p, 1);
        p += __shfl_xor_sync(0xffffffffu, p, 2);
        p += __shfl_xor_sync(0xffffffffu, p, 4);
        float e2 = __expf(p);
        redAdd4(g_buf + OFF_GATACC + (size_t)dd[j]*HID + lane*4,
                e2*xlv[j].x, e2*xlv[j].y, e2*xlv[j].z, e2*xlv[j].w);
        if ((lane & 7) == 0)
            atomicAdd(&g_buf[OFF_GSUM + (size_t)dd[j]*NH + (lane >> 3)], e2);
    }
}

// ================= TR edge pass (main stream) =================
__global__ void __launch_bounds__(256)
edge_tr_kernel(const int* __restrict__ ep, const float* __restrict__ ea,
               const float* __restrict__ tWe)
{
    const int lane = threadIdx.x & 31;
    const int warp = threadIdx.x >> 5;
    int e0 = (blockIdx.x * 8 + warp) << 2;
    if (e0 >= EP_N) return;
    int idx = 0;
    if (lane < 8) {
        int e = e0 + (lane & 3);
        if (e < EP_N) idx = ep[(lane & 4) ? EP_N + e : e];
    }
    float eav = 0.f;
    if (lane >= 8 && lane < 12) {
        int e = e0 + (lane & 3);
        if (e < EP_N) eav = ea[e];
    }
    int ss[4], dd[4]; float ev[4];
    #pragma unroll
    for (int j = 0; j < 4; j++) {
        ss[j] = __shfl_sync(0xffffffffu, idx, j);
        dd[j] = __shfl_sync(0xffffffffu, idx, 4 + j);
        ev[j] = __shfl_sync(0xffffffffu, eav, 8 + j);
    }
    float4 we = ((const float4*)tWe)[lane];
    float e2v[4];
    {
        float4 kv[4], qv[4];
        #pragma unroll
        for (int j = 0; j < 4; j++) {
            if (e0 + j < EP_N) {
                kv[j] = ((const float4*)(g_buf + OFF_K + (size_t)ss[j]*HID))[lane];
                qv[j] = ((const float4*)(g_buf + OFF_Q + (size_t)dd[j]*HID))[lane];
            }
        }
        #pragma unroll
        for (int j = 0; j < 4; j++) {
            if (e0 + j >= EP_N) { e2v[j] = 0.f; continue; }
            float e = ev[j];
            float p = qv[j].x*(kv[j].x + e*we.x) + qv[j].y*(kv[j].y + e*we.y)
                    + qv[j].z*(kv[j].z + e*we.z) + qv[j].w*(kv[j].w + e*we.w);
            p += __shfl_xor_sync(0xffffffffu, p, 1);
            p += __shfl_xor_sync(0xffffffffu, p, 2);
            p += __shfl_xor_sync(0xffffffffu, p, 4);
            e2v[j] = __expf(p * 0.17677669529663689f);
        }
    }
    float4 vv[4];
    #pragma unroll
    for (int j = 0; j < 4; j++)
        if (e0 + j < EP_N)
            vv[j] = ((const float4*)(g_buf + OFF_V + (size_t)ss[j]*HID))[lane];
    #pragma unroll
    for (int j = 0; j < 4; j++) {
        if (e0 + j >= EP_N) break;
        float e2 = e2v[j];
        float e = ev[j];
        redAdd4(g_buf + OFF_TRACC + (size_t)dd[j]*HID + lane*4,
                e2*(vv[j].x + e*we.x), e2*(vv[j].y + e*we.y),
                e2*(vv[j].z + e*we.z), e2*(vv[j].w + e*we.w));
        if ((lane & 7) == 0)
            atomicAdd(&g_buf[OFF_TSUM + (size_t)dd[j]*NH + (lane >> 3)], e2);
    }
}

// ================= SAGE scatter (side stream) =================
__global__ void __launch_bounds__(256)
sage_scatter_kernel(const int* __restrict__ ei, const float* __restrict__ x_ball)
{
    int w = blockIdx.x * 8 + (threadIdx.x >> 5);
    int e0 = w << 2;
    if (e0 >= EI_N) return;
    int lane = threadIdx.x & 31;
    int idx = 0;
    if (lane < 8) {
        int e = e0 + (lane & 3);
        if (e < EI_N) idx = ei[(lane & 4) ? EI_N + e : e];
    }
    int ss[4], dd[4];
    #pragma unroll
    for (int j = 0; j < 4; j++) {
        ss[j] = __shfl_sync(0xffffffffu, idx, j);
        dd[j] = __shfl_sync(0xffffffffu, idx, 4 + j);
    }
    float4 xb[4];
    #pragma unroll
    for (int j = 0; j < 4; j++)
        if (e0 + j < EI_N)
            xb[j] = ((const float4*)(x_ball + (size_t)ss[j]*HID))[lane];
    #pragma unroll
    for (int j = 0; j < 4; j++) {
        if (e0 + j >= EI_N) break;
        redAdd4(g_buf + OFF_CTXSUM + (size_t)dd[j]*HID + lane*4,
                xb[j].x, xb[j].y, xb[j].z, xb[j].w);
        if (lane == 0) atomicAdd(&g_buf[OFF_CNT + dd[j]], 1.0f);
    }
}

// ---------------- ball LayerNorm ----------------
__global__ void ln_ball_kernel(const float* __restrict__ xball, const float* __restrict__ gbias,
                               const float* __restrict__ g, const float* __restrict__ b,
                               float* __restrict__ out)
{
    int r = (blockIdx.x << 3) + (threadIdx.x >> 5);
    if (r >= NB) return;
    int lane = threadIdx.x & 31;
    int h = lane >> 3;
    float gs = 1.0f / (g_buf[OFF_GSUM + (size_t)r*NH + h] + 1e-16f);
    float ts = 1.0f / (g_buf[OFF_TSUM + (size_t)r*NH + h] + 1e-16f);
    float4 ga = ((const float4*)(g_buf + OFF_GATACC + (size_t)r*HID))[lane];
    float4 tr = ((const float4*)(g_buf + OFF_TRACC  + (size_t)r*HID))[lane];
    float4 sk = ((const float4*)(g_buf + OFF_SKIP   + (size_t)r*HID))[lane];
    float4 xb = ((const float4*)(xball + (size_t)r*HID))[lane];
    float4 gbv = ((const float4*)gbias)[lane];
    float4 p;
    p.x = ga.x*gs + tr.x*ts + sk.x + xb.x + gbv.x;
    p.y = ga.y*gs + tr.y*ts + sk.y + xb.y + gbv.y;
    p.z = ga.z*gs + tr.z*ts + sk.z + xb.z + gbv.z;
    p.w = ga.w*gs + tr.w*ts + sk.w + xb.w + gbv.w;
    float s = p.x + p.y + p.z + p.w;
    float sq = p.x*p.x + p.y*p.y + p.z*p.z + p.w*p.w;
    #pragma unroll
    for (int off = 16; off >= 1; off >>= 1) {
        s  += __shfl_xor_sync(0xffffffffu, s, off);
        sq += __shfl_xor_sync(0xffffffffu, sq, off);
    }
    float mu = s * (1.0f/HID);
    float var = sq * (1.0f/HID) - mu*mu;
    float rstd = rsqrtf(var + 1e-5f);
    float4 gg = ((const float4*)g)[lane];
    float4 bb = ((const float4*)b)[lane];
    float4 o;
    o.x = (p.x - mu)*rstd*gg.x + bb.x;
    o.y = (p.y - mu)*rstd*gg.y + bb.y;
    o.z = (p.z - mu)*rstd*gg.z + bb.z;
    o.w = (p.w - mu)*rstd*gg.w + bb.w;
    ((float4*)(out + (size_t)r*HID))[lane] = o;
}

// ---------------- generic LayerNorm (ctx): LN(A + B) ----------------
__global__ void ln_kernel(const float* __restrict__ A, const float* __restrict__ B,
                          const float* __restrict__ g, const float* __restrict__ b,
                          float* __restrict__ out, int n) {
    int r = (blockIdx.x << 3) + (threadIdx.x >> 5);
    if (r >= n) return;
    int lane = threadIdx.x & 31;
    float4 p = ((const float4*)(A + (size_t)r*HID))[lane];
    float4 q = ((const float4*)(B + (size_t)r*HID))[lane];
    p.x += q.x; p.y += q.y; p.z += q.z; p.w += q.w;
    float s = p.x + p.y + p.z + p.w;
    float sq = p.x*p.x + p.y*p.y + p.z*p.z + p.w*p.w;
    #pragma unroll
    for (int off = 16; off >= 1; off >>= 1) {
        s  += __shfl_xor_sync(0xffffffffu, s, off);
        sq += __shfl_xor_sync(0xffffffffu, sq, off);
    }
    float mu = s * (1.0f/HID);
    float var = sq * (1.0f/HID) - mu*mu;
    float rstd = rsqrtf(var + 1e-5f);
    float4 gg = ((const float4*)g)[lane];
    float4 bb = ((const float4*)b)[lane];
    float4 o;
    o.x = (p.x - mu)*rstd*gg.x + bb.x;
    o.y = (p.y - mu)*rstd*gg.y + bb.y;
    o.z = (p.z - mu)*rstd*gg.z + bb.z;
    o.w = (p.w - mu)*rstd*gg.w + bb.w;
    ((float4*)(out + (size_t)r*HID))[lane] = o;
}

// ---------------- launch ----------------
extern "C" void kernel_launch(void* const* d_in, const int* in_sizes, int n_in,
                              void* d_out, int out_size)
{
    const float* x_ball    = (const float*)d_in[0];
    const float* x_player  = (const float*)d_in[1];
    const float* x_context = (const float*)d_in[2];
    const int*   em   = (const int*)d_in[3];
    const int*   ep   = (const int*)d_in[4];
    const int*   ei   = (const int*)d_in[5];
    const float* ea_p = (const float*)d_in[6];
    const float* gWl  = (const float*)d_in[7];
    const float* gWr  = (const float*)d_in[8];
    const float* gatt = (const float*)d_in[9];
    const float* gb   = (const float*)d_in[10];
    const float* tWq  = (const float*)d_in[11];
    const float* tbq  = (const float*)d_in[12];
    const float* tWk  = (const float*)d_in[13];
    const float* tbk  = (const float*)d_in[14];
    const float* tWv  = (const float*)d_in[15];
    const float* tbv  = (const float*)d_in[16];
    const float* tWe  = (const float*)d_in[17];
    const float* tWs  = (const float*)d_in[18];
    const float* tbs  = (const float*)d_in[19];
    const float* sWl  = (const float*)d_in[20];
    const float* sbl  = (const float*)d_in[21];
    const float* sWr  = (const float*)d_in[22];
    const float* lbg  = (const float*)d_in[23];
    const float* lbb  = (const float*)d_in[24];
    const float* lcg  = (const float*)d_in[25];
    const float* lcb  = (const float*)d_in[26];
    float* out = (float*)d_out;

    float* base = nullptr;
    cudaGetSymbolAddress((void**)&base, g_buf);
    float* s_xl   = base + OFF_XL;
    float* s_xr   = base + OFF_XR;
    float* s_q    = base + OFF_Q;
    float* s_k    = base + OFF_K;
    float* s_v    = base + OFF_V;
    float* s_skip = base + OFF_SKIP;
    float* s_sage = base + OFF_SAGE;

    const int T = 256;

    static cudaStream_t s_side = nullptr;
    static cudaEvent_t e_begin = nullptr, e_zero = nullptr, e_A = nullptr,
                       e_gat = nullptr, e_side = nullptr;
    if (s_side == nullptr) {
        cudaStreamCreateWithFlags(&s_side, cudaStreamNonBlocking);
        cudaEventCreateWithFlags(&e_begin, cudaEventDisableTiming);
        cudaEventCreateWithFlags(&e_zero, cudaEventDisableTiming);
        cudaEventCreateWithFlags(&e_A, cudaEventDisableTiming);
        cudaEventCreateWithFlags(&e_gat, cudaEventDisableTiming);
        cudaEventCreateWithFlags(&e_side, cudaEventDisableTiming);
        cudaFuncSetAttribute(big_mma, cudaFuncAttributeMaxDynamicSharedMemorySize, SMEM_BIG);
        cudaFuncSetAttribute(sage_mma, cudaFuncAttributeMaxDynamicSharedMemorySize, SMEM_SAGE);
    }

    // ---- fork point ----
    cudaEventRecord(e_begin, 0);

    // ---- main: setup -> bigA(xr,xl) -> bigB(q,k,v,skip) -> edge_tr -> ln_ball ----
    setup_kernel<<<SETUP_GRID, T>>>(tWq, tWk, tWv, tWs, gWr, gWl, sWr, sWl);

    big_mma<<<NTILE + PTILE, 256, SMEM_BIG>>>(0, x_ball, x_player,
                                              s_q, s_k, s_v, s_skip, s_xr, s_xl,
                                              tbq, tbk, tbv, tbs);
    cudaEventRecord(e_A, 0);

    big_mma<<<NTILE, 256, SMEM_BIG>>>(1, x_ball, x_player,
                                      s_q, s_k, s_v, s_skip, s_xr, s_xl,
                                      tbq, tbk, tbv, tbs);

    // ---- side: zero (overlaps setup+bigA); after bigA, GAT edge overlaps bigB;
    //      then ctx pipeline (sage scatter / mma / ln_ctx) + player copy ----
    cudaStreamWaitEvent(s_side, e_begin, 0);
    zero_kernel<<<ZERO_GRID, T, 0, s_side>>>();
    cudaEventRecord(e_zero, s_side);
    cudaMemcpyAsync(out + (size_t)(NB+NC)*HID, x_player, (size_t)NP*HID*sizeof(float),
                    cudaMemcpyDeviceToDevice, s_side);
    sage_scatter_kernel<<<BS1, T, 0, s_side>>>(ei, x_ball);
    cudaStreamWaitEvent(s_side, e_A, 0);     // xl/xr ready (also implies setup done)
    edge_gat_kernel<<<BG1, T, 0, s_side>>>(em, gatt);
    cudaEventRecord(e_gat, s_side);
    sage_mma<<<CTILE, 256, SMEM_SAGE, s_side>>>(x_context, s_sage, sbl);
    ln_kernel<<<(NC + 7)/8, T, 0, s_side>>>(s_sage, x_context, lcg, lcb,
                                            out + (size_t)NB*HID, NC);
    cudaEventRecord(e_side, s_side);

    // ---- main continues: TR edges then ball LN ----
    cudaStreamWaitEvent(0, e_zero, 0);       // TRACC zeroed
    edge_tr_kernel<<<BT1, T>>>(ep, ea_p, tWe);
    cudaStreamWaitEvent(0, e_gat, 0);        // GATACC/GSUM complete
    ln_ball_kernel<<<(NB + 7)/8, T>>>(x_ball, gb, lbg, lbb, out);

    // join
    cudaStreamWaitEvent(0, e_side, 0);
}

// round 17
// speedup vs baseline: 1.0740x; 1.0740x over previous
#include <cuda_runtime.h>
#include <cuda_bf16.h>
#include <cstdint>

#define HID 128
#define NH 4
#define NB 60000
#define NP 2000
#define NC 4000
#define EM_N 150000
#define EP_N 300000
#define EI_N 150000
#define NTILE 469          // ceil(NB/128)
#define PTILE 16           // ceil(NP/128)
#define CTILE 32           // ceil(NC/128)

// edge pass block counts (4 edges/warp, 8 warps/block => 32 edges/block)
#define BG1 ((EM_N/4 + 7)/8)
#define BT1 ((EP_N/4 + 7)/8)
#define BS1 ((EI_N/4 + 7)/8)
#define PASS_GRID (BG1 + BT1)

// weight prep grid
#define PB ((8*16384 + 255)/256)

// ---- scratch layout (floats). Zeroed stats are CONTIGUOUS: GSUM,TSUM,CTXSUM,CNT ----
#define SZ_NBH (NB*HID)
#define OFF_XL     0
#define OFF_XR     (OFF_XL + NP*HID)
#define OFF_Q      (OFF_XR + SZ_NBH)
#define OFF_K      (OFF_Q + SZ_NBH)
#define OFF_V      (OFF_K + SZ_NBH)
#define OFF_ACC    (OFF_V + SZ_NBH)          // seeded by skip GEMM; scatters add
#define OFF_SAGE   (OFF_ACC + SZ_NBH)
#define OFF_GLOGIT (OFF_SAGE + NC*HID)
#define OFF_TLOGIT (OFF_GLOGIT + EM_N*NH)
#define OFF_GSUM   (OFF_TLOGIT + EP_N*NH)    // ---- zero range starts here ----
#define OFF_TSUM   (OFF_GSUM + NB*NH)
#define OFF_CTXSUM (OFF_TSUM + NB*NH)
#define OFF_CNT    (OFF_CTXSUM + NC*HID)
#define TOTAL_SCRATCH (OFF_CNT + NC)
#define ZSTAT_TOT (2*NB*NH + NC*HID + NC)    // 996000 floats, divisible by 4
#define ZSTAT_GRID ((ZSTAT_TOT/4 + 255)/256)

__device__ __align__(256) float g_buf[TOTAL_SCRATCH];

// pre-converted weights: 8 x {hi,lo}; order: 0=q,1=k,2=v,3=skip,4=gWr,5=gWl,6=sWr,7=sWl
#define STR 136
#define WP_ELEMS (128*STR)
__device__ __align__(1024) __nv_bfloat16 g_Wprep[8*2*WP_ELEMS];

// ---------------- PTX helpers ----------------
__device__ __forceinline__ uint32_t smem_u32(const void* p) {
    uint32_t a;
    asm("{ .reg .u64 t; cvta.to.shared.u64 t, %1; cvt.u32.u64 %0, t; }" : "=r"(a) : "l"(p));
    return a;
}
__device__ __forceinline__ void ldsm4(uint32_t& r0, uint32_t& r1, uint32_t& r2, uint32_t& r3,
                                      uint32_t addr) {
    asm volatile("ldmatrix.sync.aligned.m8n8.x4.shared.b16 {%0,%1,%2,%3}, [%4];"
                 : "=r"(r0), "=r"(r1), "=r"(r2), "=r"(r3) : "r"(addr));
}
__device__ __forceinline__ void ldsm4t(uint32_t& r0, uint32_t& r1, uint32_t& r2, uint32_t& r3,
                                       uint32_t addr) {
    asm volatile("ldmatrix.sync.aligned.m8n8.x4.trans.shared.b16 {%0,%1,%2,%3}, [%4];"
                 : "=r"(r0), "=r"(r1), "=r"(r2), "=r"(r3) : "r"(addr));
}
__device__ __forceinline__ void mma16816(float* C, const uint32_t* A, uint32_t B0, uint32_t B1) {
    asm volatile("mma.sync.aligned.m16n8k16.row.col.f32.bf16.bf16.f32 "
                 "{%0,%1,%2,%3}, {%4,%5,%6,%7}, {%8,%9}, {%0,%1,%2,%3};"
                 : "+f"(C[0]), "+f"(C[1]), "+f"(C[2]), "+f"(C[3])
                 : "r"(A[0]), "r"(A[1]), "r"(A[2]), "r"(A[3]), "r"(B0), "r"(B1));
}
#define CP_ASYNC16(sm, gm) \
    asm volatile("cp.async.ca.shared.global [%0], [%1], 16;" :: "r"(sm), "l"(gm))
#define CP_COMMIT() asm volatile("cp.async.commit_group;" ::: "memory")
#define CP_WAIT1() asm volatile("cp.async.wait_group 1;" ::: "memory")
#define CP_WAIT0() asm volatile("cp.async.wait_group 0;" ::: "memory")

// ---------------- weight prep (main, tiny) ----------------
__global__ void prepW_kernel(const float* __restrict__ w0, const float* __restrict__ w1,
                             const float* __restrict__ w2, const float* __restrict__ w3,
                             const float* __restrict__ w4, const float* __restrict__ w5,
                             const float* __restrict__ w6, const float* __restrict__ w7)
{
    int idx = blockIdx.x * 256 + threadIdx.x;
    if (idx >= 8 * 16384) return;
    int m = idx >> 14, rem = idx & 16383;
    int k = rem >> 7, n = rem & 127;
    const float* W = (m == 0) ? w0 : (m == 1) ? w1 : (m == 2) ? w2 : (m == 3) ? w3
                   : (m == 4) ? w4 : (m == 5) ? w5 : (m == 6) ? w6 : w7;
    float v = W[(size_t)k * HID + n];
    __nv_bfloat16 hi = __float2bfloat16(v);
    __nv_bfloat16 lo = __float2bfloat16(v - __bfloat162float(hi));
    g_Wprep[(size_t)(m*2 + 0)*WP_ELEMS + k*STR + n] = hi;
    g_Wprep[(size_t)(m*2 + 1)*WP_ELEMS + k*STR + n] = lo;
}

// ---------------- zero stats (side stream): GSUM,TSUM,CTXSUM,CNT contiguous ----------------
__global__ void zero_stats_kernel() {
    size_t i = ((size_t)blockIdx.x * 256 + threadIdx.x) * 4;
    if (i + 3 < ZSTAT_TOT)
        *(float4*)(g_buf + OFF_GSUM + i) = make_float4(0.f, 0.f, 0.f, 0.f);
    else
        for (size_t k = i; k < ZSTAT_TOT; k++) g_buf[OFF_GSUM + k] = 0.f;
}

// ---------------- fused 6-output HMMA GEMM ----------------
#define SMA_H 0
#define SMA_L 34816
#define SMW0  69632
#define SMW1  139264
#define SMEM_BIG5 208896

__device__ __forceinline__ void stageW_async(uint32_t smW, int widx, int tid) {
    const char* gh = (const char*)g_Wprep + (size_t)(widx*2)*WP_ELEMS*2;
    const char* gl = gh + WP_ELEMS*2;
    for (int j = tid; j < 2176; j += 256) {
        CP_ASYNC16(smW + j*16, gh + j*16);
        CP_ASYNC16(smW + 34816 + j*16, gl + j*16);
    }
}

__global__ void __launch_bounds__(256)
big5_mma(const float* __restrict__ xball, const float* __restrict__ xplayer,
         float* __restrict__ o0, float* __restrict__ o1, float* __restrict__ o2,
         float* __restrict__ o3, float* __restrict__ o4, float* __restrict__ o5,
         const float* __restrict__ b0, const float* __restrict__ b1,
         const float* __restrict__ b2, const float* __restrict__ b3)
{
    extern __shared__ char smem[];
    const uint32_t sb = smem_u32(smem);
    const int tid = threadIdx.x, lane = tid & 31, warp = tid >> 5;
    const int wm = warp >> 1, wn = warp & 1;
    const bool player = (blockIdx.x >= NTILE);
    const int tile = player ? (blockIdx.x - NTILE) : blockIdx.x;
    const int rbase = tile * 128;
    const int nrows = player ? NP : NB;
    const float* Asrc = player ? xplayer : xball;
    const int nw = player ? 1 : 5;   // weights 0..4 for ball (q,k,v,skip,gWr); 5 (gWl) for player

    for (int idx = tid; idx < 8192; idx += 256) {
        int row = idx >> 6, kp = idx & 63;
        int grow = rbase + row;
        float2 v = make_float2(0.f, 0.f);
        if (grow < nrows) v = ((const float2*)(Asrc + (size_t)grow * HID))[kp];
        __nv_bfloat162 h2 = __float22bfloat162_rn(v);
        float2 lo = make_float2(v.x - __bfloat162float(h2.x),
                                v.y - __bfloat162float(h2.y));
        __nv_bfloat162 l2 = __float22bfloat162_rn(lo);
        uint32_t off = (uint32_t)(row * STR + kp * 2) * 2;
        *(uint32_t*)(smem + SMA_H + off) = *(uint32_t*)&h2;
        *(uint32_t*)(smem + SMA_L + off) = *(uint32_t*)&l2;
    }

    stageW_async(sb + SMW0, player ? 5 : 0, tid);
    CP_COMMIT();

    float*       outs[5]   = {o0, o1, o2, o3, o4};
    const float* biases[5] = {b0, b1, b2, b3, nullptr};

    const int gid = lane >> 2, tig = lane & 3;
    const int sub = lane >> 3, lr = lane & 7;
    const int f_r = ((sub & 1) << 3) + lr;
    const int f_c = (sub >> 1) << 3;

    for (int i = 0; i < nw; i++) {
        if (i + 1 < nw) {
            stageW_async(sb + (((i+1) & 1) ? SMW1 : SMW0), i + 1, tid);
            CP_COMMIT();
            CP_WAIT1();
        } else {
            CP_WAIT0();
        }
        __syncthreads();

        const uint32_t wbase = sb + ((i & 1) ? SMW1 : SMW0);

        float acc[2][8][4];
        #pragma unroll
        for (int mt = 0; mt < 2; mt++)
            #pragma unroll
            for (int j = 0; j < 8; j++)
                #pragma unroll
                for (int c = 0; c < 4; c++) acc[mt][j][c] = 0.f;

        #pragma unroll
        for (int ks = 0; ks < 8; ks++) {
            const int K0 = ks * 16;
            uint32_t ah[2][4], al[2][4];
            #pragma unroll
            for (int mt = 0; mt < 2; mt++) {
                uint32_t ad = sb + SMA_H +
                    (uint32_t)((wm*32 + mt*16 + f_r) * STR + K0 + f_c) * 2;
                ldsm4(ah[mt][0], ah[mt][1], ah[mt][2], ah[mt][3], ad);
                ldsm4(al[mt][0], al[mt][1], al[mt][2], al[mt][3], ad + (SMA_L - SMA_H));
            }
            uint32_t bh[4][4], bl[4][4];
            #pragma unroll
            for (int nt = 0; nt < 4; nt++) {
                uint32_t wd = wbase +
                    (uint32_t)((K0 + f_r) * STR + wn*64 + nt*16 + f_c) * 2;
                ldsm4t(bh[nt][0], bh[nt][1], bh[nt][2], bh[nt][3], wd);
                ldsm4t(bl[nt][0], bl[nt][1], bl[nt][2], bl[nt][3], wd + 34816);
            }
            #pragma unroll
            for (int mt = 0; mt < 2; mt++)
                #pragma unroll
                for (int nt = 0; nt < 4; nt++)
                    #pragma unroll
                    for (int h = 0; h < 2; h++) {
                        float* C = acc[mt][nt*2 + h];
                        mma16816(C, ah[mt], bh[nt][2*h], bh[nt][2*h+1]);
                        mma16816(C, ah[mt], bl[nt][2*h], bl[nt][2*h+1]);
                        mma16816(C, al[mt], bh[nt][2*h], bh[nt][2*h+1]);
                    }
        }

        const float* bias = player ? nullptr : biases[i];
        float* outp = player ? o5 : outs[i];
        #pragma unroll
        for (int mt = 0; mt < 2; mt++) {
            int r0g = rbase + wm*32 + mt*16 + gid;
            #pragma unroll
            for (int j = 0; j < 8; j++) {
                int cn = wn*64 + j*8 + tig*2;
                float bx = bias ? bias[cn]   : 0.f;
                float by = bias ? bias[cn+1] : 0.f;
                if (r0g < nrows)
                    *(float2*)(outp + (size_t)r0g*HID + cn) =
                        make_float2(acc[mt][j][0] + bx, acc[mt][j][1] + by);
                if (r0g + 8 < nrows)
                    *(float2*)(outp + (size_t)(r0g+8)*HID + cn) =
                        make_float2(acc[mt][j][2] + bx, acc[mt][j][3] + by);
            }
        }
        __syncthreads();
    }
}

// ---------------- sage HMMA: s_sage = x_ctx@sWr + (ctxsum/cnt)@sWl + sbl ----------------
#define SMEM_SAGE 139264

__global__ void __launch_bounds__(256)
sage_mma(const float* __restrict__ xctx, float* __restrict__ outp,
         const float* __restrict__ sbl)
{
    extern __shared__ char smem[];
    const uint32_t sb = smem_u32(smem);
    const int tid = threadIdx.x, lane = tid & 31, warp = tid >> 5;
    const int wm = warp >> 1, wn = warp & 1;
    const int rbase = blockIdx.x * 128;

    const int gid = lane >> 2, tig = lane & 3;
    const int sub = lane >> 3, lr = lane & 7;
    const int f_r = ((sub & 1) << 3) + lr;
    const int f_c = (sub >> 1) << 3;

    float acc[2][8][4];
    #pragma unroll
    for (int mt = 0; mt < 2; mt++)
        #pragma unroll
        for (int j = 0; j < 8; j++)
            #pragma unroll
            for (int c = 0; c < 4; c++) acc[mt][j][c] = 0.f;

    for (int it = 0; it < 2; it++) {
        const int widx = 6 + it;
        for (int idx = tid; idx < 8192; idx += 256) {
            int row = idx >> 6, kp = idx & 63;
            int grow = rbase + row;
            float2 v = make_float2(0.f, 0.f);
            if (grow < NC) {
                if (it == 0) {
                    v = ((const float2*)(xctx + (size_t)grow * HID))[kp];
                } else {
                    v = ((const float2*)(g_buf + OFF_CTXSUM + (size_t)grow * HID))[kp];
                    float rc = 1.0f / fmaxf(g_buf[OFF_CNT + grow], 1.0f);
                    v.x *= rc; v.y *= rc;
                }
            }
            __nv_bfloat162 h2 = __float22bfloat162_rn(v);
            float2 lo = make_float2(v.x - __bfloat162float(h2.x),
                                    v.y - __bfloat162float(h2.y));
            __nv_bfloat162 l2 = __float22bfloat162_rn(lo);
            uint32_t off = (uint32_t)(row * STR + kp * 2) * 2;
            *(uint32_t*)(smem + SMA_H + off) = *(uint32_t*)&h2;
            *(uint32_t*)(smem + SMA_L + off) = *(uint32_t*)&l2;
        }
        {
            const uint4* gh = (const uint4*)((const char*)g_Wprep + (size_t)(widx*2)*WP_ELEMS*2);
            const uint4* gl = (const uint4*)((const char*)g_Wprep + (size_t)(widx*2+1)*WP_ELEMS*2);
            uint4* dh = (uint4*)(smem + SMW0);
            uint4* dl = (uint4*)(smem + SMW0 + 34816);
            for (int j = tid; j < 2176; j += 256) { dh[j] = gh[j]; dl[j] = gl[j]; }
        }
        __syncthreads();

        #pragma unroll
        for (int ks = 0; ks < 8; ks++) {
            const int K0 = ks * 16;
            uint32_t ah[2][4], al[2][4];
            #pragma unroll
            for (int mt = 0; mt < 2; mt++) {
                uint32_t ad = sb + SMA_H +
                    (uint32_t)((wm*32 + mt*16 + f_r) * STR + K0 + f_c) * 2;
                ldsm4(ah[mt][0], ah[mt][1], ah[mt][2], ah[mt][3], ad);
                ldsm4(al[mt][0], al[mt][1], al[mt][2], al[mt][3], ad + (SMA_L - SMA_H));
            }
            uint32_t bh[4][4], bl[4][4];
            #pragma unroll
            for (int nt = 0; nt < 4; nt++) {
                uint32_t wd = sb + SMW0 +
                    (uint32_t)((K0 + f_r) * STR + wn*64 + nt*16 + f_c) * 2;
                ldsm4t(bh[nt][0], bh[nt][1], bh[nt][2], bh[nt][3], wd);
                ldsm4t(bl[nt][0], bl[nt][1], bl[nt][2], bl[nt][3], wd + 34816);
            }
            #pragma unroll
            for (int mt = 0; mt < 2; mt++)
                #pragma unroll
                for (int nt = 0; nt < 4; nt++)
                    #pragma unroll
                    for (int h = 0; h < 2; h++) {
                        float* C = acc[mt][nt*2 + h];
                        mma16816(C, ah[mt], bh[nt][2*h], bh[nt][2*h+1]);
                        mma16816(C, ah[mt], bl[nt][2*h], bl[nt][2*h+1]);
                        mma16816(C, al[mt], bh[nt][2*h], bh[nt][2*h+1]);
                    }
        }
        __syncthreads();
    }

    #pragma unroll
    for (int mt = 0; mt < 2; mt++) {
        int r0g = rbase + wm*32 + mt*16 + gid;
        #pragma unroll
        for (int j = 0; j < 8; j++) {
            int cn = wn*64 + j*8 + tig*2;
            float bx = sbl[cn], by = sbl[cn+1];
            if (r0g < NC)
                *(float2*)(outp + (size_t)r0g*HID + cn) =
                    make_float2(acc[mt][j][0] + bx, acc[mt][j][1] + by);
            if (r0g + 8 < NC)
                *(float2*)(outp + (size_t)(r0g+8)*HID + cn) =
                    make_float2(acc[mt][j][2] + bx, acc[mt][j][3] + by);
        }
    }
}

// ---------------- helpers ----------------
__device__ __forceinline__ void redAdd4(float* p, float a, float b, float c, float d) {
    asm volatile("red.global.add.v4.f32 [%0], {%1,%2,%3,%4};"
                 :: "l"(p), "f"(a), "f"(b), "f"(c), "f"(d) : "memory");
}

// ================= edge pass 1: logits + exp + segment sums (GAT, TR) =================
__global__ void __launch_bounds__(256, 6)
pass1_kernel(const int* __restrict__ em, const float* __restrict__ att,
             const int* __restrict__ ep, const float* __restrict__ ea,
             const float* __restrict__ tWe)
{
    const int lane = threadIdx.x & 31;
    const int warp = threadIdx.x >> 5;
    const unsigned bx = blockIdx.x;

    if (bx < BG1) {
        int e0 = (bx * 8 + warp) << 2;
        if (e0 >= EM_N) return;
        int idx = 0;
        if (lane < 8) {
            int e = e0 + (lane & 3);
            if (e < EM_N) idx = em[(lane & 4) ? EM_N + e : e];
        }
        int ss[4], dd[4];
        #pragma unroll
        for (int j = 0; j < 4; j++) {
            ss[j] = __shfl_sync(0xffffffffu, idx, j);
            dd[j] = __shfl_sync(0xffffffffu, idx, 4 + j);
        }
        float4 at = ((const float4*)att)[lane];
        float4 xlv[4], xrv[4];
        #pragma unroll
        for (int j = 0; j < 4; j++) {
            if (e0 + j < EM_N) {
                xlv[j] = ((const float4*)(g_buf + OFF_XL + (size_t)ss[j]*HID))[lane];
                xrv[j] = ((const float4*)(g_buf + OFF_XR + (size_t)dd[j]*HID))[lane];
            }
        }
        #pragma unroll
        for (int j = 0; j < 4; j++) {
            if (e0 + j >= EM_N) break;
            float ex = xlv[j].x + xrv[j].x; ex = ex > 0.f ? ex : 0.2f*ex;
            float ey = xlv[j].y + xrv[j].y; ey = ey > 0.f ? ey : 0.2f*ey;
            float ez = xlv[j].z + xrv[j].z; ez = ez > 0.f ? ez : 0.2f*ez;
            float ew = xlv[j].w + xrv[j].w; ew = ew > 0.f ? ew : 0.2f*ew;
            float p = ex*at.x + ey*at.y + ez*at.z + ew*at.w;
            p += __shfl_xor_sync(0xffffffffu, p, 1);
            p += __shfl_xor_sync(0xffffffffu, p, 2);
            p += __shfl_xor_sync(0xffffffffu, p, 4);
            if ((lane & 7) == 0) {
                int h = lane >> 3;
                float e2 = __expf(p);
                g_buf[OFF_GLOGIT + (size_t)(e0 + j)*NH + h] = e2;
                atomicAdd(&g_buf[OFF_GSUM + (size_t)dd[j]*NH + h], e2);
            }
        }
    } else {
        int e0 = ((bx - BG1) * 8 + warp) << 2;
        if (e0 >= EP_N) return;
        int idx = 0;
        if (lane < 8) {
            int e = e0 + (lane & 3);
            if (e < EP_N) idx = ep[(lane & 4) ? EP_N + e : e];
        }
        float eav = 0.f;
        if (lane >= 8 && lane < 12) {
            int e = e0 + (lane & 3);
            if (e < EP_N) eav = ea[e];
        }
        int ss[4], dd[4]; float ev[4];
        #pragma unroll
        for (int j = 0; j < 4; j++) {
            ss[j] = __shfl_sync(0xffffffffu, idx, j);
            dd[j] = __shfl_sync(0xffffffffu, idx, 4 + j);
            ev[j] = __shfl_sync(0xffffffffu, eav, 8 + j);
        }
        float4 we = ((const float4*)tWe)[lane];
        float4 kv[4], qv[4];
        #pragma unroll
        for (int j = 0; j < 4; j++) {
            if (e0 + j < EP_N) {
                kv[j] = ((const float4*)(g_buf + OFF_K + (size_t)ss[j]*HID))[lane];
                qv[j] = ((const float4*)(g_buf + OFF_Q + (size_t)dd[j]*HID))[lane];
            }
        }
        #pragma unroll
        for (int j = 0; j < 4; j++) {
            if (e0 + j >= EP_N) break;
            float e = ev[j];
            float p = qv[j].x*(kv[j].x + e*we.x) + qv[j].y*(kv[j].y + e*we.y)
                    + qv[j].z*(kv[j].z + e*we.z) + qv[j].w*(kv[j].w + e*we.w);
            p += __shfl_xor_sync(0xffffffffu, p, 1);
            p += __shfl_xor_sync(0xffffffffu, p, 2);
            p += __shfl_xor_sync(0xffffffffu, p, 4);
            if ((lane & 7) == 0) {
                int h = lane >> 3;
                float e2 = __expf(p * 0.17677669529663689f);
                g_buf[OFF_TLOGIT + (size_t)(e0 + j)*NH + h] = e2;
                atomicAdd(&g_buf[OFF_TSUM + (size_t)dd[j]*NH + h], e2);
            }
        }
    }
}

// ================= edge pass 2: weighted scatters into ACC (GAT, TR) =================
__global__ void __launch_bounds__(256, 6)
pass2_kernel(const int* __restrict__ em,
             const int* __restrict__ ep, const float* __restrict__ ea,
             const float* __restrict__ tWe)
{
    const int lane = threadIdx.x & 31;
    const int warp = threadIdx.x >> 5;
    const unsigned bx = blockIdx.x;

    if (bx < BG1) {
        int e0 = (bx * 8 + warp) << 2;
        if (e0 >= EM_N) return;
        int idx = 0;
        if (lane < 8) {
            int e = e0 + (lane & 3);
            if (e < EM_N) idx = em[(lane & 4) ? EM_N + e : e];
        }
        int ss[4], dd[4];
        #pragma unroll
        for (int j = 0; j < 4; j++) {
            ss[j] = __shfl_sync(0xffffffffu, idx, j);
            dd[j] = __shfl_sync(0xffffffffu, idx, 4 + j);
        }
        int h = lane >> 3;
        float lg[4], sm[4]; float4 xl[4];
        #pragma unroll
        for (int j = 0; j < 4; j++) {
            if (e0 + j < EM_N) {
                lg[j] = g_buf[OFF_GLOGIT + (size_t)(e0 + j)*NH + h];
                sm[j] = g_buf[OFF_GSUM + (size_t)dd[j]*NH + h];
                xl[j] = ((const float4*)(g_buf + OFF_XL + (size_t)ss[j]*HID))[lane];
            }
        }
        #pragma unroll
        for (int j = 0; j < 4; j++) {
            if (e0 + j >= EM_N) break;
            float alpha = lg[j] / (sm[j] + 1e-16f);
            redAdd4(g_buf + OFF_ACC + (size_t)dd[j]*HID + lane*4,
                    xl[j].x*alpha, xl[j].y*alpha, xl[j].z*alpha, xl[j].w*alpha);
        }
    } else {
        int e0 = ((bx - BG1) * 8 + warp) << 2;
        if (e0 >= EP_N) return;
        int idx = 0;
        if (lane < 8) {
            int e = e0 + (lane & 3);
            if (e < EP_N) idx = ep[(lane & 4) ? EP_N + e : e];
        }
        float eav = 0.f;
        if (lane >= 8 && lane < 12) {
            int e = e0 + (lane & 3);
            if (e < EP_N) eav = ea[e];
        }
        int ss[4], dd[4]; float ev[4];
        #pragma unroll
        for (int j = 0; j < 4; j++) {
            ss[j] = __shfl_sync(0xffffffffu, idx, j);
            dd[j] = __shfl_sync(0xffffffffu, idx, 4 + j);
            ev[j] = __shfl_sync(0xffffffffu, eav, 8 + j);
        }
        int h = lane >> 3;
        float4 we = ((const float4*)tWe)[lane];
        float lg[4], sm[4]; float4 vv[4];
        #pragma unroll
        for (int j = 0; j < 4; j++) {
            if (e0 + j < EP_N) {
                lg[j] = g_buf[OFF_TLOGIT + (size_t)(e0 + j)*NH + h];
                sm[j] = g_buf[OFF_TSUM + (size_t)dd[j]*NH + h];
                vv[j] = ((const float4*)(g_buf + OFF_V + (size_t)ss[j]*HID))[lane];
            }
        }
        #pragma unroll
        for (int j = 0; j < 4; j++) {
            if (e0 + j >= EP_N) break;
            float alpha = lg[j] / (sm[j] + 1e-16f);
            float e = ev[j];
            redAdd4(g_buf + OFF_ACC + (size_t)dd[j]*HID + lane*4,
                    (vv[j].x + e*we.x)*alpha, (vv[j].y + e*we.y)*alpha,
                    (vv[j].z + e*we.z)*alpha, (vv[j].w + e*we.w)*alpha);
        }
    }
}

// ================= SAGE scatter (side stream) =================
__global__ void __launch_bounds__(256, 6)
sage_scatter_kernel(const int* __restrict__ ei, const float* __restrict__ x_ball)
{
    int w = blockIdx.x * 8 + (threadIdx.x >> 5);
    int e0 = w << 2;
    if (e0 >= EI_N) return;
    int lane = threadIdx.x & 31;
    int idx = 0;
    if (lane < 8) {
        int e = e0 + (lane & 3);
        if (e < EI_N) idx = ei[(lane & 4) ? EI_N + e : e];
    }
    int ss[4], dd[4];
    #pragma unroll
    for (int j = 0; j < 4; j++) {
        ss[j] = __shfl_sync(0xffffffffu, idx, j);
        dd[j] = __shfl_sync(0xffffffffu, idx, 4 + j);
    }
    float4 xb[4];
    #pragma unroll
    for (int j = 0; j < 4; j++)
        if (e0 + j < EI_N)
            xb[j] = ((const float4*)(x_ball + (size_t)ss[j]*HID))[lane];
    #pragma unroll
    for (int j = 0; j < 4; j++) {
        if (e0 + j >= EI_N) break;
        redAdd4(g_buf + OFF_CTXSUM + (size_t)dd[j]*HID + lane*4,
                xb[j].x, xb[j].y, xb[j].z, xb[j].w);
        if (lane == 0) atomicAdd(&g_buf[OFF_CNT + dd[j]], 1.0f);
    }
}

// ---------------- LayerNorm: out = LN(A + B [+ bcast]) ----------------
__global__ void ln_kernel(const float* __restrict__ A, const float* __restrict__ B,
                          const float* __restrict__ bcast, const float* __restrict__ g,
                          const float* __restrict__ b, float* __restrict__ out, int n) {
    int r = (blockIdx.x << 3) + (threadIdx.x >> 5);
    if (r >= n) return;
    int lane = threadIdx.x & 31;
    float4 p = ((const float4*)(A + (size_t)r*HID))[lane];
    float4 q = ((const float4*)(B + (size_t)r*HID))[lane];
    p.x += q.x; p.y += q.y; p.z += q.z; p.w += q.w;
    if (bcast) {
        float4 c4 = ((const float4*)bcast)[lane];
        p.x += c4.x; p.y += c4.y; p.z += c4.z; p.w += c4.w;
    }
    float s = p.x + p.y + p.z + p.w;
    float sq = p.x*p.x + p.y*p.y + p.z*p.z + p.w*p.w;
    #pragma unroll
    for (int off = 16; off >= 1; off >>= 1) {
        s  += __shfl_xor_sync(0xffffffffu, s, off);
        sq += __shfl_xor_sync(0xffffffffu, sq, off);
    }
    float mu = s * (1.0f/HID);
    float var = sq * (1.0f/HID) - mu*mu;
    float rstd = rsqrtf(var + 1e-5f);
    float4 gg = ((const float4*)g)[lane];
    float4 bb = ((const float4*)b)[lane];
    float4 o;
    o.x = (p.x - mu)*rstd*gg.x + bb.x;
    o.y = (p.y - mu)*rstd*gg.y + bb.y;
    o.z = (p.z - mu)*rstd*gg.z + bb.z;
    o.w = (p.w - mu)*rstd*gg.w + bb.w;
    ((float4*)(out + (size_t)r*HID))[lane] = o;
}

// ---------------- launch ----------------
extern "C" void kernel_launch(void* const* d_in, const int* in_sizes, int n_in,
                              void* d_out, int out_size)
{
    const float* x_ball    = (const float*)d_in[0];
    const float* x_player  = (const float*)d_in[1];
    const float* x_context = (const float*)d_in[2];
    const int*   em   = (const int*)d_in[3];
    const int*   ep   = (const int*)d_in[4];
    const int*   ei   = (const int*)d_in[5];
    const float* ea_p = (const float*)d_in[6];
    const float* gWl  = (const float*)d_in[7];
    const float* gWr  = (const float*)d_in[8];
    const float* gatt = (const float*)d_in[9];
    const float* gb   = (const float*)d_in[10];
    const float* tWq  = (const float*)d_in[11];
    const float* tbq  = (const float*)d_in[12];
    const float* tWk  = (const float*)d_in[13];
    const float* tbk  = (const float*)d_in[14];
    const float* tWv  = (const float*)d_in[15];
    const float* tbv  = (const float*)d_in[16];
    const float* tWe  = (const float*)d_in[17];
    const float* tWs  = (const float*)d_in[18];
    const float* tbs  = (const float*)d_in[19];
    const float* sWl  = (const float*)d_in[20];
    const float* sbl  = (const float*)d_in[21];
    const float* sWr  = (const float*)d_in[22];
    const float* lbg  = (const float*)d_in[23];
    const float* lbb  = (const float*)d_in[24];
    const float* lcg  = (const float*)d_in[25];
    const float* lcb  = (const float*)d_in[26];
    float* out = (float*)d_out;

    float* base = nullptr;
    cudaGetSymbolAddress((void**)&base, g_buf);
    float* s_xl   = base + OFF_XL;
    float* s_xr   = base + OFF_XR;
    float* s_q    = base + OFF_Q;
    float* s_k    = base + OFF_K;
    float* s_v    = base + OFF_V;
    float* s_acc  = base + OFF_ACC;
    float* s_sage = base + OFF_SAGE;

    const int T = 256;

    static cudaStream_t s_side = nullptr;
    static cudaEvent_t e_begin = nullptr, e_prep = nullptr, e_zero = nullptr, e_side = nullptr;
    if (s_side == nullptr) {
        cudaStreamCreateWithFlags(&s_side, cudaStreamNonBlocking);
        cudaEventCreateWithFlags(&e_begin, cudaEventDisableTiming);
        cudaEventCreateWithFlags(&e_prep, cudaEventDisableTiming);
        cudaEventCreateWithFlags(&e_zero, cudaEventDisableTiming);
        cudaEventCreateWithFlags(&e_side, cudaEventDisableTiming);
        cudaFuncSetAttribute(big5_mma, cudaFuncAttributeMaxDynamicSharedMemorySize, SMEM_BIG5);
        cudaFuncSetAttribute(sage_mma, cudaFuncAttributeMaxDynamicSharedMemorySize, SMEM_SAGE);
    }

    // ---- fork point ----
    cudaEventRecord(e_begin, 0);

    // ---- main: prepW -> big5 -> (wait zero) pass1 -> pass2 -> ln_ball ----
    prepW_kernel<<<PB, T>>>(tWq, tWk, tWv, tWs, gWr, gWl, sWr, sWl);
    cudaEventRecord(e_prep, 0);

    big5_mma<<<NTILE + PTILE, 256, SMEM_BIG5>>>(x_ball, x_player,
                                                s_q, s_k, s_v, s_acc, s_xr, s_xl,
                                                tbq, tbk, tbv, tbs);

    // ---- side: zero stats (overlaps prep+big5) -> player copy -> sage scatter ->
    //      (wait prep) sage_mma -> ln_ctx ----
    cudaStreamWaitEvent(s_side, e_begin, 0);
    zero_stats_kernel<<<ZSTAT_GRID, T, 0, s_side>>>();
    cudaEventRecord(e_zero, s_side);
    cudaMemcpyAsync(out + (size_t)(NB+NC)*HID, x_player, (size_t)NP*HID*sizeof(float),
                    cudaMemcpyDeviceToDevice, s_side);
    sage_scatter_kernel<<<BS1, T, 0, s_side>>>(ei, x_ball);
    cudaStreamWaitEvent(s_side, e_prep, 0);
    sage_mma<<<CTILE, 256, SMEM_SAGE, s_side>>>(x_context, s_sage, sbl);
    ln_kernel<<<(NC + 7)/8, T, 0, s_side>>>(s_sage, x_context, nullptr, lcg, lcb,
                                            out + (size_t)NB*HID, NC);
    cudaEventRecord(e_side, s_side);

    // ---- main continues ----
    cudaStreamWaitEvent(0, e_zero, 0);       // GSUM/TSUM zeroed
    pass1_kernel<<<PASS_GRID, T>>>(em, gatt, ep, ea_p, tWe);
    pass2_kernel<<<PASS_GRID, T>>>(em, ep, ea_p, tWe);
    ln_kernel<<<(NB + 7)/8, T>>>(s_acc, x_ball, gb, lbg, lbb, out, NB);

    // join
    cudaStreamWaitEvent(0, e_side, 0);
}